// round 9
// baseline (speedup 1.0000x reference)
#include <cuda_runtime.h>

// B=16, H=128, W=128, C=256, P=8192
//   in_tensor: (B,H,W,C) f32   indices: (B,P,2) f32 (dim0->H, dim1->W)
//   out: (B,P,C) f32
//
// Bilinear: out = p1*(1-mx)(1-my) + p2*mx(1-my) + p3*(1-mx)my + p4*mx*my
//   p1=in[b,fh,fw]  p2=in[b,ch,fw]  p3=in[b,fh,cw]  p4=in[b,ch,cw]
//
// R6 findings: DRAM traffic already at analytic floor (~336MB); latency-bound,
// occupancy fell to 59% because regs=34 > 32 broke the 8-blocks/SM fit.
// This version: force 8 blocks/SM (<=32 regs) + slimmer address math
// (corner offsets as conditional deltas from r1 — exact for in-range coords
// since integral coordinate => ceil==floor and that corner's weight is 0).

#define GB (16)
#define GH (128)
#define GW (128)
#define GC (256)
#define GP (8192)

__global__ __launch_bounds__(256, 8) void grid_sample_kernel(
    const float* __restrict__ in_tensor,
    const float* __restrict__ indices,
    float* __restrict__ out)
{
    const int gid   = blockIdx.x * 256 + threadIdx.x;
    const int point = gid >> 5;        // global point id: 0 .. B*P-1
    const int lane  = gid & 31;        // first float4 slot (second = lane+32)

    const int b = point >> 13;         // / P

    const float2 ind = __ldg(((const float2*)indices) + point);

    const float fx = floorf(ind.x);
    const float fy = floorf(ind.y);
    const int ifx = (int)fx;           // H floor
    const int ify = (int)fy;           // W floor

    const float mx = ind.x - fx;
    const float my = ind.y - fy;
    const float omx = 1.0f - mx;
    const float omy = 1.0f - my;

    const float w1 = omx * omy;
    const float w2 = mx  * omy;
    const float w3 = omx * my;
    const float w4 = mx  * my;

    // ceil corner = floor corner + 1 iff fractional part > 0; when fractional
    // part == 0 the matching weight is 0 and ceil==floor, so delta 0 is exact.
    const int dh = (mx > 0.0f) ? (GW * (GC / 4)) : 0;  // +1 row in H
    const int dw = (my > 0.0f) ? (GC / 4) : 0;          // +1 cell in W

    const float4* r1 = ((const float4*)in_tensor)
                     + (size_t)b * (GH * GW * (GC / 4))
                     + (size_t)(ifx * GW + ify) * (GC / 4) + lane;
    const float4* r2 = r1 + dh;
    const float4* r3 = r1 + dw;
    const float4* r4 = r1 + dh + dw;

    // 8 independent 16B loads -> MLP=8 per thread
    const float4 v1a = __ldg(r1);
    const float4 v2a = __ldg(r2);
    const float4 v3a = __ldg(r3);
    const float4 v4a = __ldg(r4);
    const float4 v1b = __ldg(r1 + 32);
    const float4 v2b = __ldg(r2 + 32);
    const float4 v3b = __ldg(r3 + 32);
    const float4 v4b = __ldg(r4 + 32);

    float4 oa, ob;
    oa.x = v1a.x * w1 + v2a.x * w2 + v3a.x * w3 + v4a.x * w4;
    oa.y = v1a.y * w1 + v2a.y * w2 + v3a.y * w3 + v4a.y * w4;
    oa.z = v1a.z * w1 + v2a.z * w2 + v3a.z * w3 + v4a.z * w4;
    oa.w = v1a.w * w1 + v2a.w * w2 + v3a.w * w3 + v4a.w * w4;

    ob.x = v1b.x * w1 + v2b.x * w2 + v3b.x * w3 + v4b.x * w4;
    ob.y = v1b.y * w1 + v2b.y * w2 + v3b.y * w3 + v4b.y * w4;
    ob.z = v1b.z * w1 + v2b.z * w2 + v3b.z * w3 + v4b.z * w4;
    ob.w = v1b.w * w1 + v2b.w * w2 + v3b.w * w3 + v4b.w * w4;

    // Write-once output: streaming store keeps L2 for gather reuse.
    float4* o = ((float4*)out) + (size_t)point * (GC / 4) + lane;
    __stcs(o,      oa);
    __stcs(o + 32, ob);
}

extern "C" void kernel_launch(void* const* d_in, const int* in_sizes, int n_in,
                              void* d_out, int out_size)
{
    const float* in_tensor = (const float*)d_in[0];
    const float* indices   = (const float*)d_in[1];
    float*       out       = (float*)d_out;

    const int total_points = GB * GP;                 // 131072
    const int blocks = (total_points * 32) / 256;     // 16384
    grid_sample_kernel<<<blocks, 256>>>(in_tensor, indices, out);
}

// round 10
// speedup vs baseline: 1.0645x; 1.0645x over previous
#include <cuda_runtime.h>
#include <cstdint>

// B=16, H=128, W=128, C=256, P=8192
//   in_tensor: (B,H,W,C) f32   indices: (B,P,2) f32 (dim0->H, dim1->W)
//   out: (B,P,C) f32
//
// Bilinear: out = p1*(1-mx)(1-my) + p2*mx(1-my) + p3*(1-mx)my + p4*mx*my
//
// R9 findings: LDG path is latency/queue-bound at ~62-66% DRAM; traffic is at
// the analytic floor. This version replaces per-thread LDG gathers with
// cp.async.bulk (TMA) 1KB row copies into a 4-stage smem ring, paced by
// mbarrier complete_tx. Outstanding bytes/SM rises ~40x; DRAM should saturate.

#define GB 16
#define GH 128
#define GW 128
#define GC 256
#define GP 8192

#define NTHREADS 128
#define PPC 32                 // points per CTA (all same batch: 32 | 8192)
#define STAGES 4
#define PTS_PER_STAGE 2
#define NITER (PPC / PTS_PER_STAGE)          // 16
#define ROW_BYTES (GC * 4)                   // 1024
#define STAGE_BYTES (PTS_PER_STAGE * 4 * ROW_BYTES)  // 8192

__device__ __forceinline__ uint32_t smem_u32(const void* p) {
    uint32_t a;
    asm("{ .reg .u64 t; cvta.to.shared.u64 t, %1; cvt.u32.u64 %0, t; }"
        : "=r"(a) : "l"(p));
    return a;
}

__device__ __forceinline__ void mbar_init(uint32_t bar, uint32_t count) {
    asm volatile("mbarrier.init.shared.b64 [%0], %1;" :: "r"(bar), "r"(count) : "memory");
}

__device__ __forceinline__ void mbar_expect_tx(uint32_t bar, uint32_t bytes) {
    asm volatile("mbarrier.arrive.expect_tx.shared.b64 _, [%0], %1;"
                 :: "r"(bar), "r"(bytes) : "memory");
}

__device__ __forceinline__ void bulk_g2s(uint32_t dst, const void* src,
                                         uint32_t bytes, uint32_t bar) {
    asm volatile(
        "cp.async.bulk.shared::cta.global.mbarrier::complete_tx::bytes "
        "[%0], [%1], %2, [%3];"
        :: "r"(dst), "l"(src), "r"(bytes), "r"(bar) : "memory");
}

__device__ __forceinline__ void mbar_wait(uint32_t bar, uint32_t parity) {
    asm volatile(
        "{\n\t"
        ".reg .pred P;\n\t"
        "WAIT_%=:\n\t"
        "mbarrier.try_wait.parity.acquire.cta.shared::cta.b64 P, [%0], %1, 0x989680;\n\t"
        "@P bra DONE_%=;\n\t"
        "bra WAIT_%=;\n\t"
        "DONE_%=:\n\t"
        "}"
        :: "r"(bar), "r"(parity) : "memory");
}

__global__ __launch_bounds__(NTHREADS) void grid_sample_tma(
    const float* __restrict__ in_tensor,
    const float* __restrict__ indices,
    float* __restrict__ out)
{
    __shared__ alignas(16) unsigned char stage_buf[STAGES * STAGE_BYTES];
    __shared__ alignas(8)  unsigned long long mbar[STAGES];
    __shared__ float2 sidx[PPC];

    const int tid    = threadIdx.x;
    const int cta    = blockIdx.x;
    const int point0 = cta * PPC;                  // global first point
    const int b      = point0 >> 13;               // batch (constant per CTA)

    // Stage the 32 index pairs into smem (producer + consumers read from here)
    if (tid < PPC)
        sidx[tid] = __ldg(((const float2*)indices) + point0 + tid);

    const uint32_t mbar0  = smem_u32(&mbar[0]);
    const uint32_t sbuf0  = smem_u32(&stage_buf[0]);

    if (tid == 0) {
        #pragma unroll
        for (int s = 0; s < STAGES; s++) mbar_init(mbar0 + s * 8, 1);
    }
    __syncthreads();   // mbar init + sidx visible to all

    // Batch image base, byte addressed
    const char* img = (const char*)in_tensor + (size_t)b * (GH * GW) * ROW_BYTES;

    // Producer: issue the 8 bulk copies (2 points x 4 corner rows) for iter it
    auto issue = [&](int it) {
        const int s = it & (STAGES - 1);
        const uint32_t bar = mbar0 + s * 8;
        mbar_expect_tx(bar, STAGE_BYTES);
        #pragma unroll
        for (int k = 0; k < PTS_PER_STAGE; k++) {
            const float2 ind = sidx[it * PTS_PER_STAGE + k];
            const float fx = floorf(ind.x);
            const float fy = floorf(ind.y);
            const int row  = (int)fx * GW + (int)fy;
            // ceil corner == floor corner when coord integral (weight 0)
            const int dh = (ind.x > fx) ? (GW * ROW_BYTES) : 0;
            const int dw = (ind.y > fy) ? ROW_BYTES : 0;
            const char* base = img + (size_t)row * ROW_BYTES;
            const uint32_t dst = sbuf0 + s * STAGE_BYTES + k * 4 * ROW_BYTES;
            bulk_g2s(dst,                 base,           ROW_BYTES, bar);
            bulk_g2s(dst + 1 * ROW_BYTES, base + dh,      ROW_BYTES, bar);
            bulk_g2s(dst + 2 * ROW_BYTES, base + dw,      ROW_BYTES, bar);
            bulk_g2s(dst + 3 * ROW_BYTES, base + dh + dw, ROW_BYTES, bar);
        }
    };

    // Prologue: fill the ring
    if (tid == 0) {
        #pragma unroll
        for (int it = 0; it < STAGES; it++) issue(it);
    }

    // Consumer mapping: 2 points/stage, 64 threads each (one float4 slot)
    const int k    = tid >> 6;        // point within stage (0/1)
    const int slot = tid & 63;        // float4 slot in C=256 row

    float4* out4 = (float4*)out;

    for (int it = 0; it < NITER; it++) {
        const int s  = it & (STAGES - 1);
        const int ph = (it >> 2) & 1;          // NITER/STAGES parity flips
        mbar_wait(mbar0 + s * 8, ph);

        const int p = it * PTS_PER_STAGE + k;  // local point id
        const float2 ind = sidx[p];
        const float mx = ind.x - floorf(ind.x);
        const float my = ind.y - floorf(ind.y);
        const float omx = 1.0f - mx;
        const float omy = 1.0f - my;
        const float w1 = omx * omy;
        const float w2 = mx  * omy;
        const float w3 = omx * my;
        const float w4 = mx  * my;

        const float4* sb = (const float4*)(stage_buf + s * STAGE_BYTES + k * 4 * ROW_BYTES);
        const float4 v1 = sb[slot];
        const float4 v2 = sb[64 + slot];
        const float4 v3 = sb[128 + slot];
        const float4 v4 = sb[192 + slot];

        float4 o;
        o.x = v1.x * w1 + v2.x * w2 + v3.x * w3 + v4.x * w4;
        o.y = v1.y * w1 + v2.y * w2 + v3.y * w3 + v4.y * w4;
        o.z = v1.z * w1 + v2.z * w2 + v3.z * w3 + v4.z * w4;
        o.w = v1.w * w1 + v2.w * w2 + v3.w * w3 + v4.w * w4;

        __stcs(out4 + (size_t)(point0 + p) * (GC / 4) + slot, o);

        __syncthreads();                        // stage s fully consumed
        if (tid == 0 && it + STAGES < NITER) issue(it + STAGES);
    }
}

extern "C" void kernel_launch(void* const* d_in, const int* in_sizes, int n_in,
                              void* d_out, int out_size)
{
    const float* in_tensor = (const float*)d_in[0];
    const float* indices   = (const float*)d_in[1];
    float*       out       = (float*)d_out;

    const int blocks = (GB * GP) / PPC;   // 131072/32 = 4096
    grid_sample_tma<<<blocks, NTHREADS>>>(in_tensor, indices, out);
}